// round 11
// baseline (speedup 1.0000x reference)
#include <cuda_runtime.h>
#include <cuda_bf16.h>
#include <cstdint>
#include <math.h>

// GMM score via HMMA (mma.sync bf16), symmetry 2-split GEMM, 2 CTAs/SM.
//   G[n,(c,j)] = sum_k A_c[j,k] xh_k        (GEMM on xh only; B in hi+lo splits)
//   x^T A x    = sum_j (xh+2*xl)_j G_j  (+ xl^T A xl dropped, ~2^-18)
//   d[n,c]     = quad + L[n,c],  L = -2 b_c.x + k_c  (exact fp32, prologue, smem-fed)
//   score      = exp(sum_c w_c log d)

#define ROWB    144           // bytes per smem row (72 bf16, 64 used) — conflict-free ldmatrix
#define XHI_B   18432         // 128 rows * 144
#define HALF_BB 18432
#define CHUNK_B 36864         // hi + lo image of one B chunk

__device__ __align__(16) unsigned char g_B[8][CHUNK_B];
__device__ __align__(16) float g_bm2[1024];   // -2 * b_c[j],  [c*64 + j]
__device__ __align__(8) float g_kc[16];

__device__ __forceinline__ uint32_t smem_u32(const void* p) {
    uint32_t a;
    asm("{ .reg .u64 t; cvta.to.shared.u64 t, %1; cvt.u32.u64 %0, t; }" : "=r"(a) : "l"(p));
    return a;
}
__device__ __forceinline__ uint32_t pk(__nv_bfloat16 a, __nv_bfloat16 b) {
    __nv_bfloat162 t(a, b);
    return *reinterpret_cast<uint32_t*>(&t);
}

#define HMMA(acc, a, b0, b1)                                                  \
    asm volatile("mma.sync.aligned.m16n8k16.row.col.f32.bf16.bf16.f32 "       \
        "{%0,%1,%2,%3},{%4,%5,%6,%7},{%8,%9},{%0,%1,%2,%3};"                  \
        : "+f"((acc)[0]), "+f"((acc)[1]), "+f"((acc)[2]), "+f"((acc)[3])      \
        : "r"((a)[0]), "r"((a)[1]), "r"((a)[2]), "r"((a)[3]), "r"(b0), "r"(b1))

// ---------------- precomp 1: pack B hi/lo + b vectors ----------------
__global__ void precomp1(const float* __restrict__ A, const float* __restrict__ Mn) {
    if (blockIdx.x < 128) {
        const int idx   = blockIdx.x * 256 + threadIdx.x;   // 0..32767
        const int chunk = idx >> 12;
        const int rem   = idx & 4095;
        const int row   = rem >> 5;
        const int kp    = rem & 31;
        const int comp  = chunk * 2 + (row >> 6);
        const int j     = row & 63;
        const float2 v = *(const float2*)(A + comp * 4096 + j * 64 + kp * 2);
        __nv_bfloat16 h0 = __float2bfloat16(v.x), h1 = __float2bfloat16(v.y);
        __nv_bfloat16 l0 = __float2bfloat16(v.x - __bfloat162float(h0));
        __nv_bfloat16 l1 = __float2bfloat16(v.y - __bfloat162float(h1));
        *(uint32_t*)(g_B[chunk] + row * ROWB + kp * 4)           = pk(h0, h1);
        *(uint32_t*)(g_B[chunk] + HALF_BB + row * ROWB + kp * 4) = pk(l0, l1);
    } else {
        // b_c[j] = A_c[j,:] . m_c
        const int bi = (blockIdx.x - 128) * 256 + threadIdx.x;  // 0..1023
        const int c = bi >> 6, j = bi & 63;
        const float4* Ar = (const float4*)(A + c * 4096 + j * 64);
        const float4* mr = (const float4*)(Mn + c * 64);
        float s0 = 0, s1 = 0, s2 = 0, s3 = 0;
        #pragma unroll
        for (int t = 0; t < 16; t++) {
            float4 a = Ar[t], m = mr[t];
            s0 = fmaf(a.x, m.x, s0); s1 = fmaf(a.y, m.y, s1);
            s2 = fmaf(a.z, m.z, s2); s3 = fmaf(a.w, m.w, s3);
        }
        g_bm2[bi] = -2.0f * ((s0 + s1) + (s2 + s3));
    }
}

// ---------------- precomp 2: k_c = m_c^T b_c ----------------
__global__ void precomp2(const float* __restrict__ Mn) {
    const int c = threadIdx.x;
    if (c < 16) {
        float acc = 0.0f;
        #pragma unroll
        for (int j = 0; j < 64; j++)
            acc = fmaf(Mn[c * 64 + j], -0.5f * g_bm2[c * 64 + j], acc);
        g_kc[c] = acc;
    }
}

// ---------------- main kernel ----------------
// smem: Xhi [0,18432) | 2 x B buf | w 64B | L[128][16] 8KB | bm2 4KB
#define SM_B0  XHI_B                          // 18432
#define SM_W   (XHI_B + 2 * CHUNK_B)          // 92160
#define SM_L   (SM_W + 64)                    // 92224
#define SM_BM  (SM_L + 8192)                  // 100416
#define SMEM_BYTES (SM_BM + 4096)             // 104512

__global__ void __launch_bounds__(256, 2)
gmm_hmma_kernel(const float* __restrict__ X, const float* __restrict__ W,
                float* __restrict__ out, int N)
{
    extern __shared__ unsigned char smem[];
    const uint32_t sb = smem_u32(smem);
    const int tid  = threadIdx.x;
    const int wid  = tid >> 5;
    const int lane = tid & 31;
    const int base = blockIdx.x * 128;

    // prefetch B chunk 0
    {
        size_t gsrc = __cvta_generic_to_global(g_B[0]);
        const uint32_t dst = sb + SM_B0;
        #pragma unroll
        for (int i = 0; i < 9; i++) {
            int o = (i * 256 + tid) * 16;
            asm volatile("cp.async.cg.shared.global [%0], [%1], 16;"
                         :: "r"(dst + o), "l"(gsrc + o));
        }
        asm volatile("cp.async.commit_group;");
    }
    if (tid < 16) *(float*)(smem + SM_W + 4 * tid) = W[tid];
    ((float4*)(smem + SM_BM))[tid] = ((const float4*)g_bm2)[tid];  // 4KB bm2 -> smem

    // stage Xhi: row = tid>>1, half = tid&1 covers 32 cols
    {
        const int row = tid >> 1, half = tid & 1;
        const float4* xg = (const float4*)(X + (size_t)(base + row) * 64 + half * 32);
        unsigned char* rp = smem + row * ROWB + half * 64;
        #pragma unroll
        for (int q = 0; q < 8; q++) {
            float4 v = xg[q];
            *(uint2*)(rp + q * 8) = make_uint2(
                pk(__float2bfloat16(v.x), __float2bfloat16(v.y)),
                pk(__float2bfloat16(v.z), __float2bfloat16(v.w)));
        }
    }
    __syncthreads();   // bm2 + Xhi visible

    const int r0g = wid * 16 + (lane >> 2);   // this thread's quad row (0..127 in CTA)
    const int jb  = 2 * (lane & 3);           // quad j-offset

    // Pass A: wx = xh + 2*xl  AND quad-partial L for comps 0..7 (Lp 16 regs)
    float wx[2][16];
    {
        float Lp[2][8];
        #pragma unroll
        for (int rh = 0; rh < 2; rh++)
            #pragma unroll
            for (int c = 0; c < 8; c++) Lp[rh][c] = 0.0f;
        #pragma unroll
        for (int rh = 0; rh < 2; rh++) {
            const float* xr = X + (size_t)(base + r0g + rh * 8) * 64 + jb;
            #pragma unroll
            for (int q = 0; q < 8; q++) {
                float2 v = *(const float2*)(xr + q * 8);
                __nv_bfloat16 h0 = __float2bfloat16(v.x), h1 = __float2bfloat16(v.y);
                wx[rh][2*q]   = __bfloat162float(h0) + 2.0f * (v.x - __bfloat162float(h0));
                wx[rh][2*q+1] = __bfloat162float(h1) + 2.0f * (v.y - __bfloat162float(h1));
                const int j = q * 8 + jb;
                #pragma unroll
                for (int c = 0; c < 8; c++) {
                    float2 b = *(const float2*)(smem + SM_BM + (c * 64 + j) * 4);
                    Lp[rh][c] = fmaf(v.x, b.x, fmaf(v.y, b.y, Lp[rh][c]));
                }
            }
        }
        #pragma unroll
        for (int rh = 0; rh < 2; rh++)
            #pragma unroll
            for (int cp = 0; cp < 4; cp++) {
                float a = Lp[rh][2*cp], b = Lp[rh][2*cp + 1];
                a += __shfl_xor_sync(0xFFFFFFFFu, a, 1); a += __shfl_xor_sync(0xFFFFFFFFu, a, 2);
                b += __shfl_xor_sync(0xFFFFFFFFu, b, 1); b += __shfl_xor_sync(0xFFFFFFFFu, b, 2);
                if ((lane & 3) == 0) {
                    float2 kc = __ldg((const float2*)(g_kc + 2 * cp));
                    *(float2*)(smem + SM_L + ((r0g + rh * 8) * 16 + 2 * cp) * 4) =
                        make_float2(a + kc.x, b + kc.y);
                }
            }
    }
    // Pass B: comps 8..15 (x re-read, L1-hot)
    {
        float Lp[2][8];
        #pragma unroll
        for (int rh = 0; rh < 2; rh++)
            #pragma unroll
            for (int c = 0; c < 8; c++) Lp[rh][c] = 0.0f;
        #pragma unroll
        for (int rh = 0; rh < 2; rh++) {
            const float* xr = X + (size_t)(base + r0g + rh * 8) * 64 + jb;
            #pragma unroll
            for (int q = 0; q < 8; q++) {
                float2 v = *(const float2*)(xr + q * 8);
                const int j = q * 8 + jb;
                #pragma unroll
                for (int c = 0; c < 8; c++) {
                    float2 b = *(const float2*)(smem + SM_BM + ((c + 8) * 64 + j) * 4);
                    Lp[rh][c] = fmaf(v.x, b.x, fmaf(v.y, b.y, Lp[rh][c]));
                }
            }
        }
        #pragma unroll
        for (int rh = 0; rh < 2; rh++)
            #pragma unroll
            for (int cp = 0; cp < 4; cp++) {
                float a = Lp[rh][2*cp], b = Lp[rh][2*cp + 1];
                a += __shfl_xor_sync(0xFFFFFFFFu, a, 1); a += __shfl_xor_sync(0xFFFFFFFFu, a, 2);
                b += __shfl_xor_sync(0xFFFFFFFFu, b, 1); b += __shfl_xor_sync(0xFFFFFFFFu, b, 2);
                if ((lane & 3) == 0) {
                    float2 kc = __ldg((const float2*)(g_kc + 8 + 2 * cp));
                    *(float2*)(smem + SM_L + ((r0g + rh * 8) * 16 + 8 + 2 * cp) * 4) =
                        make_float2(a + kc.x, b + kc.y);
                }
            }
    }
    __syncthreads();   // sL complete

    // A-fragments (Xhi only)
    uint32_t Ahi[4][4];
    {
        const int arow = wid * 16 + ((lane >> 3) & 1) * 8 + (lane & 7);
        const uint32_t coff = (lane >> 4) * 16;
        #pragma unroll
        for (int s = 0; s < 4; s++) {
            uint32_t ah = sb + arow * ROWB + coff + s * 32;
            asm volatile("ldmatrix.sync.aligned.m8n8.x4.shared.b16 {%0,%1,%2,%3}, [%4];"
                : "=r"(Ahi[s][0]), "=r"(Ahi[s][1]), "=r"(Ahi[s][2]), "=r"(Ahi[s][3]) : "r"(ah));
        }
    }

    float la0 = 0.0f, la1 = 0.0f;

    for (int c = 0; c < 8; c++) {
        asm volatile("cp.async.wait_group 0;");
        __syncthreads();

        if (c + 1 < 8) {
            size_t gsrc = __cvta_generic_to_global(g_B[c + 1]);
            const uint32_t dst = sb + SM_B0 + ((c + 1) & 1) * CHUNK_B;
            #pragma unroll
            for (int i = 0; i < 9; i++) {
                int o = (i * 256 + tid) * 16;
                asm volatile("cp.async.cg.shared.global [%0], [%1], 16;"
                             :: "r"(dst + o), "l"(gsrc + o));
            }
            asm volatile("cp.async.commit_group;");
        }

        // L values for this chunk's 2 comps, 2 row-groups (broadcast within quad)
        const float2 L0 = *(const float2*)(smem + SM_L + (r0g * 16 + 2 * c) * 4);
        const float2 L1 = *(const float2*)(smem + SM_L + ((r0g + 8) * 16 + 2 * c) * 4);

        const uint32_t Bb = sb + SM_B0 + (c & 1) * CHUNK_B
                          + ((lane >> 4) * 8 + (lane & 7)) * ROWB + ((lane >> 3) & 1) * 16;

        #pragma unroll
        for (int half = 0; half < 2; half++) {
            const int cc = 2 * c + half;
            float acc[8][4];
            #pragma unroll
            for (int t = 0; t < 8; t++) { acc[t][0]=0.f; acc[t][1]=0.f; acc[t][2]=0.f; acc[t][3]=0.f; }

            #pragma unroll
            for (int t2 = 0; t2 < 4; t2++) {
                #pragma unroll
                for (int s = 0; s < 4; s++) {
                    uint32_t bh0, bh1, bh2, bh3, bl0, bl1, bl2, bl3;
                    const uint32_t ab = Bb + (half * 64 + t2 * 16) * ROWB + s * 32;
                    asm volatile("ldmatrix.sync.aligned.m8n8.x4.shared.b16 {%0,%1,%2,%3}, [%4];"
                                 : "=r"(bh0), "=r"(bh1), "=r"(bh2), "=r"(bh3) : "r"(ab));
                    asm volatile("ldmatrix.sync.aligned.m8n8.x4.shared.b16 {%0,%1,%2,%3}, [%4];"
                                 : "=r"(bl0), "=r"(bl1), "=r"(bl2), "=r"(bl3) : "r"(ab + HALF_BB));
                    HMMA(acc[2*t2],   Ahi[s], bh0, bh1);
                    HMMA(acc[2*t2+1], Ahi[s], bh2, bh3);
                    HMMA(acc[2*t2],   Ahi[s], bl0, bl1);
                    HMMA(acc[2*t2+1], Ahi[s], bl2, bl3);
                }
            }

            // epilogue: p = sum_j wx_j G_j; d = p + L
            float p0 = 0.f, p1 = 0.f;
            #pragma unroll
            for (int t = 0; t < 8; t++) {
                p0 = fmaf(wx[0][t*2],   acc[t][0], p0);
                p0 = fmaf(wx[0][t*2+1], acc[t][1], p0);
                p1 = fmaf(wx[1][t*2],   acc[t][2], p1);
                p1 = fmaf(wx[1][t*2+1], acc[t][3], p1);
            }
            p0 += __shfl_xor_sync(0xFFFFFFFFu, p0, 1); p0 += __shfl_xor_sync(0xFFFFFFFFu, p0, 2);
            p1 += __shfl_xor_sync(0xFFFFFFFFu, p1, 1); p1 += __shfl_xor_sync(0xFFFFFFFFu, p1, 2);

            const float wc = *(float*)(smem + SM_W + 4 * cc);
            la0 = fmaf(wc, __logf(p0 + (half ? L0.y : L0.x)), la0);
            la1 = fmaf(wc, __logf(p1 + (half ? L1.y : L1.x)), la1);
        }
    }

    if ((lane & 3) == 0) {
        out[base + r0g]     = __expf(la0);
        out[base + r0g + 8] = __expf(la1);
    }
}

// ---------------- launch ----------------
extern "C" void kernel_launch(void* const* d_in, const int* in_sizes, int n_in,
                              void* d_out, int out_size)
{
    const float* X     = (const float*)d_in[0];   // [N, 64]
    const float* Ainv  = (const float*)d_in[1];   // [16, 64, 64]
    const float* Means = (const float*)d_in[2];   // [16, 64]
    const float* W     = (const float*)d_in[3];   // [16]
    float* out = (float*)d_out;

    const int N = in_sizes[0] / 64;

    cudaFuncSetAttribute(gmm_hmma_kernel, cudaFuncAttributeMaxDynamicSharedMemorySize, SMEM_BYTES);

    precomp1<<<132, 256>>>(Ainv, Means);
    precomp2<<<1, 32>>>(Means);
    gmm_hmma_kernel<<<N / 128, 256, SMEM_BYTES>>>(X, W, out, N);
}

// round 12
// speedup vs baseline: 1.0364x; 1.0364x over previous
#include <cuda_runtime.h>
#include <cuda_bf16.h>
#include <cstdint>
#include <math.h>

// GMM score via HMMA (mma.sync bf16), symmetry 2-split GEMM, 2 CTAs/SM.
//   G[n,(c,j)] = sum_k A_c[j,k] xh_k        (GEMM on xh only; B in hi+lo splits)
//   x^T A x    = sum_j (xh+2*xl)_j G_j  (+ xl^T A xl dropped, ~2^-18)
//   d[n,c]     = quad + x.(-2 b_c) + k_c   (linear: exact fp32, in-loop, transient regs)
//   score      = exp(sum_c w_c log d)

#define ROWB    144           // bytes per smem row (72 bf16, 64 used) — conflict-free ldmatrix
#define XHI_B   18432         // 128 rows * 144
#define HALF_BB 18432
#define CHUNK_B 36864         // hi + lo image of one B chunk

__device__ __align__(16) unsigned char g_B[8][CHUNK_B];
__device__ __align__(16) float g_bm2[1024];   // -2 * b_c[j],  [c*64 + j]
__device__ __align__(8) float g_kc[16];

__device__ __forceinline__ uint32_t smem_u32(const void* p) {
    uint32_t a;
    asm("{ .reg .u64 t; cvta.to.shared.u64 t, %1; cvt.u32.u64 %0, t; }" : "=r"(a) : "l"(p));
    return a;
}
__device__ __forceinline__ uint32_t pk(__nv_bfloat16 a, __nv_bfloat16 b) {
    __nv_bfloat162 t(a, b);
    return *reinterpret_cast<uint32_t*>(&t);
}

#define HMMA(acc, a, b0, b1)                                                  \
    asm volatile("mma.sync.aligned.m16n8k16.row.col.f32.bf16.bf16.f32 "       \
        "{%0,%1,%2,%3},{%4,%5,%6,%7},{%8,%9},{%0,%1,%2,%3};"                  \
        : "+f"((acc)[0]), "+f"((acc)[1]), "+f"((acc)[2]), "+f"((acc)[3])      \
        : "r"((a)[0]), "r"((a)[1]), "r"((a)[2]), "r"((a)[3]), "r"(b0), "r"(b1))

// ---------------- precomp 1: pack B hi/lo + b vectors ----------------
__global__ void precomp1(const float* __restrict__ A, const float* __restrict__ Mn) {
    if (blockIdx.x < 128) {
        const int idx   = blockIdx.x * 256 + threadIdx.x;   // 0..32767
        const int chunk = idx >> 12;
        const int rem   = idx & 4095;
        const int row   = rem >> 5;
        const int kp    = rem & 31;
        const int comp  = chunk * 2 + (row >> 6);
        const int j     = row & 63;
        const float2 v = *(const float2*)(A + comp * 4096 + j * 64 + kp * 2);
        __nv_bfloat16 h0 = __float2bfloat16(v.x), h1 = __float2bfloat16(v.y);
        __nv_bfloat16 l0 = __float2bfloat16(v.x - __bfloat162float(h0));
        __nv_bfloat16 l1 = __float2bfloat16(v.y - __bfloat162float(h1));
        *(uint32_t*)(g_B[chunk] + row * ROWB + kp * 4)           = pk(h0, h1);
        *(uint32_t*)(g_B[chunk] + HALF_BB + row * ROWB + kp * 4) = pk(l0, l1);
    } else {
        // b_c[j] = A_c[j,:] . m_c
        const int bi = (blockIdx.x - 128) * 256 + threadIdx.x;  // 0..1023
        const int c = bi >> 6, j = bi & 63;
        const float4* Ar = (const float4*)(A + c * 4096 + j * 64);
        const float4* mr = (const float4*)(Mn + c * 64);
        float s0 = 0, s1 = 0, s2 = 0, s3 = 0;
        #pragma unroll
        for (int t = 0; t < 16; t++) {
            float4 a = Ar[t], m = mr[t];
            s0 = fmaf(a.x, m.x, s0); s1 = fmaf(a.y, m.y, s1);
            s2 = fmaf(a.z, m.z, s2); s3 = fmaf(a.w, m.w, s3);
        }
        g_bm2[bi] = -2.0f * ((s0 + s1) + (s2 + s3));
    }
}

// ---------------- precomp 2: k_c = m_c^T b_c ----------------
__global__ void precomp2(const float* __restrict__ Mn) {
    const int c = threadIdx.x;
    if (c < 16) {
        float acc = 0.0f;
        #pragma unroll
        for (int j = 0; j < 64; j++)
            acc = fmaf(Mn[c * 64 + j], -0.5f * g_bm2[c * 64 + j], acc);
        g_kc[c] = acc;
    }
}

// ---------------- main kernel ----------------
// smem: Xhi [0,18432) | 2 x B buf | w 64B | kc 64B | bm2 4KB
#define SM_B0  XHI_B                          // 18432
#define SM_W   (XHI_B + 2 * CHUNK_B)          // 92160
#define SM_KC  (SM_W + 64)                    // 92224
#define SM_BM  (SM_KC + 64)                   // 92288
#define SMEM_BYTES (SM_BM + 4096)             // 96384

__global__ void __launch_bounds__(256, 2)
gmm_hmma_kernel(const float* __restrict__ X, const float* __restrict__ W,
                float* __restrict__ out, int N)
{
    extern __shared__ unsigned char smem[];
    const uint32_t sb = smem_u32(smem);
    const int tid  = threadIdx.x;
    const int wid  = tid >> 5;
    const int lane = tid & 31;
    const int base = blockIdx.x * 128;

    // prefetch B chunk 0
    {
        size_t gsrc = __cvta_generic_to_global(g_B[0]);
        const uint32_t dst = sb + SM_B0;
        #pragma unroll
        for (int i = 0; i < 9; i++) {
            int o = (i * 256 + tid) * 16;
            asm volatile("cp.async.cg.shared.global [%0], [%1], 16;"
                         :: "r"(dst + o), "l"(gsrc + o));
        }
        asm volatile("cp.async.commit_group;");
    }
    if (tid < 16) {
        *(float*)(smem + SM_W  + 4 * tid) = W[tid];
        *(float*)(smem + SM_KC + 4 * tid) = g_kc[tid];
    }
    ((float4*)(smem + SM_BM))[tid] = ((const float4*)g_bm2)[tid];  // 4KB bm2 -> smem

    // stage Xhi: row = tid>>1, half = tid&1 covers 32 cols
    {
        const int row = tid >> 1, half = tid & 1;
        const float4* xg = (const float4*)(X + (size_t)(base + row) * 64 + half * 32);
        unsigned char* rp = smem + row * ROWB + half * 64;
        #pragma unroll
        for (int q = 0; q < 8; q++) {
            float4 v = xg[q];
            *(uint2*)(rp + q * 8) = make_uint2(
                pk(__float2bfloat16(v.x), __float2bfloat16(v.y)),
                pk(__float2bfloat16(v.z), __float2bfloat16(v.w)));
        }
    }

    const int r0g = wid * 16 + (lane >> 2);   // this thread's quad row (0..127 in CTA)
    const int jb  = 2 * (lane & 3);           // quad j-offset

    // quad weights straight from global X:  wx = xh + 2*xl   (as in the 186us variant)
    float wx[2][16];
    {
        #pragma unroll
        for (int rh = 0; rh < 2; rh++) {
            const float* xr = X + (size_t)(base + r0g + rh * 8) * 64 + jb;
            #pragma unroll
            for (int q = 0; q < 8; q++) {
                float2 v = *(const float2*)(xr + q * 8);
                __nv_bfloat16 h0 = __float2bfloat16(v.x), h1 = __float2bfloat16(v.y);
                wx[rh][2*q]   = __bfloat162float(h0) + 2.0f * (v.x - __bfloat162float(h0));
                wx[rh][2*q+1] = __bfloat162float(h1) + 2.0f * (v.y - __bfloat162float(h1));
            }
        }
    }
    __syncthreads();

    // A-fragments (Xhi only)
    uint32_t Ahi[4][4];
    {
        const int arow = wid * 16 + ((lane >> 3) & 1) * 8 + (lane & 7);
        const uint32_t coff = (lane >> 4) * 16;
        #pragma unroll
        for (int s = 0; s < 4; s++) {
            uint32_t ah = sb + arow * ROWB + coff + s * 32;
            asm volatile("ldmatrix.sync.aligned.m8n8.x4.shared.b16 {%0,%1,%2,%3}, [%4];"
                : "=r"(Ahi[s][0]), "=r"(Ahi[s][1]), "=r"(Ahi[s][2]), "=r"(Ahi[s][3]) : "r"(ah));
        }
    }

    float la0 = 0.0f, la1 = 0.0f;

    for (int c = 0; c < 8; c++) {
        asm volatile("cp.async.wait_group 0;");
        __syncthreads();

        if (c + 1 < 8) {
            size_t gsrc = __cvta_generic_to_global(g_B[c + 1]);
            const uint32_t dst = sb + SM_B0 + ((c + 1) & 1) * CHUNK_B;
            #pragma unroll
            for (int i = 0; i < 9; i++) {
                int o = (i * 256 + tid) * 16;
                asm volatile("cp.async.cg.shared.global [%0], [%1], 16;"
                             :: "r"(dst + o), "l"(gsrc + o));
            }
            asm volatile("cp.async.commit_group;");
        }

        // exact linear term (transient): lp[rh][half] = quad-partial x.(-2 b_cc)
        // x re-read from global (L1-hot after chunk 0), b from smem fp32.
        float lp00 = 0.f, lp01 = 0.f, lp10 = 0.f, lp11 = 0.f;
        {
            const float* xr0 = X + (size_t)(base + r0g) * 64 + jb;
            const float* xr1 = xr0 + 8 * 64;
            #pragma unroll
            for (int q = 0; q < 8; q++) {
                float2 v0 = *(const float2*)(xr0 + q * 8);
                float2 v1 = *(const float2*)(xr1 + q * 8);
                float2 b0 = *(const float2*)(smem + SM_BM + ((2*c) * 64 + q * 8 + jb) * 4);
                float2 b1 = *(const float2*)(smem + SM_BM + ((2*c + 1) * 64 + q * 8 + jb) * 4);
                lp00 = fmaf(v0.x, b0.x, fmaf(v0.y, b0.y, lp00));
                lp01 = fmaf(v0.x, b1.x, fmaf(v0.y, b1.y, lp01));
                lp10 = fmaf(v1.x, b0.x, fmaf(v1.y, b0.y, lp10));
                lp11 = fmaf(v1.x, b1.x, fmaf(v1.y, b1.y, lp11));
            }
        }
        const float2 kc = *(const float2*)(smem + SM_KC + 8 * c);

        const uint32_t Bb = sb + SM_B0 + (c & 1) * CHUNK_B
                          + ((lane >> 4) * 8 + (lane & 7)) * ROWB + ((lane >> 3) & 1) * 16;

        #pragma unroll
        for (int half = 0; half < 2; half++) {
            const int cc = 2 * c + half;
            float acc[8][4];
            #pragma unroll
            for (int t = 0; t < 8; t++) { acc[t][0]=0.f; acc[t][1]=0.f; acc[t][2]=0.f; acc[t][3]=0.f; }

            #pragma unroll
            for (int t2 = 0; t2 < 4; t2++) {
                #pragma unroll
                for (int s = 0; s < 4; s++) {
                    uint32_t bh0, bh1, bh2, bh3, bl0, bl1, bl2, bl3;
                    const uint32_t ab = Bb + (half * 64 + t2 * 16) * ROWB + s * 32;
                    asm volatile("ldmatrix.sync.aligned.m8n8.x4.shared.b16 {%0,%1,%2,%3}, [%4];"
                                 : "=r"(bh0), "=r"(bh1), "=r"(bh2), "=r"(bh3) : "r"(ab));
                    asm volatile("ldmatrix.sync.aligned.m8n8.x4.shared.b16 {%0,%1,%2,%3}, [%4];"
                                 : "=r"(bl0), "=r"(bl1), "=r"(bl2), "=r"(bl3) : "r"(ab + HALF_BB));
                    HMMA(acc[2*t2],   Ahi[s], bh0, bh1);
                    HMMA(acc[2*t2+1], Ahi[s], bh2, bh3);
                    HMMA(acc[2*t2],   Ahi[s], bl0, bl1);
                    HMMA(acc[2*t2+1], Ahi[s], bl2, bl3);
                }
            }

            // epilogue: p seeded with quad-partial linear; shfl reduces quad+linear together
            float p0 = half ? lp01 : lp00;
            float p1 = half ? lp11 : lp10;
            #pragma unroll
            for (int t = 0; t < 8; t++) {
                p0 = fmaf(wx[0][t*2],   acc[t][0], p0);
                p0 = fmaf(wx[0][t*2+1], acc[t][1], p0);
                p1 = fmaf(wx[1][t*2],   acc[t][2], p1);
                p1 = fmaf(wx[1][t*2+1], acc[t][3], p1);
            }
            p0 += __shfl_xor_sync(0xFFFFFFFFu, p0, 1); p0 += __shfl_xor_sync(0xFFFFFFFFu, p0, 2);
            p1 += __shfl_xor_sync(0xFFFFFFFFu, p1, 1); p1 += __shfl_xor_sync(0xFFFFFFFFu, p1, 2);

            const float wc = *(float*)(smem + SM_W + 4 * cc);
            const float kk = half ? kc.y : kc.x;
            la0 = fmaf(wc, __logf(p0 + kk), la0);
            la1 = fmaf(wc, __logf(p1 + kk), la1);
        }
    }

    if ((lane & 3) == 0) {
        out[base + r0g]     = __expf(la0);
        out[base + r0g + 8] = __expf(la1);
    }
}

// ---------------- launch ----------------
extern "C" void kernel_launch(void* const* d_in, const int* in_sizes, int n_in,
                              void* d_out, int out_size)
{
    const float* X     = (const float*)d_in[0];   // [N, 64]
    const float* Ainv  = (const float*)d_in[1];   // [16, 64, 64]
    const float* Means = (const float*)d_in[2];   // [16, 64]
    const float* W     = (const float*)d_in[3];   // [16]
    float* out = (float*)d_out;

    const int N = in_sizes[0] / 64;

    cudaFuncSetAttribute(gmm_hmma_kernel, cudaFuncAttributeMaxDynamicSharedMemorySize, SMEM_BYTES);

    precomp1<<<132, 256>>>(Ainv, Means);
    precomp2<<<1, 32>>>(Means);
    gmm_hmma_kernel<<<N / 128, 256, SMEM_BYTES>>>(X, W, out, N);
}